// round 15
// baseline (speedup 1.0000x reference)
#include <cuda_runtime.h>
#include <cuda_bf16.h>
#include <cstdint>
#include <cstddef>

// ---------------------------------------------------------------------------
// Problem constants
// ---------------------------------------------------------------------------
#define NG    128
#define GSZ   128
#define DIM   512
#define NTOT  (NG * GSZ)               // 16384
#define NPAIR (GSZ * (GSZ - 1) / 2)    // 8128
#define NOUT  (NG * NPAIR)             // 1,040,384

// GEMM tiling: 128x128 CTA tile, 256 threads, 2 CTAs/SM
#define BM 128
#define BN 128
#define BK 64
#define KT (DIM / BK)                  // 8 k-chunks per tile
#define NSTG 3
#define THREADS 256
#define NITEMS 8256                    // # of 128x128 tiles with tj >= ti

#define SA_BYTES (BM * BK * 2)         // 16 KB
#define SB_BYTES (BN * BK * 2)         // 16 KB
#define SOFF_B   (NSTG * SA_BYTES)
#define SOFF_MBAR (NSTG * (SA_BYTES + SB_BYTES))     // 98304
#define SMEM_TOTAL (SOFF_MBAR + 64)                  // + mbarriers

// ---------------------------------------------------------------------------
// Device globals
// ---------------------------------------------------------------------------
__device__ __align__(16) __nv_bfloat16 g_Ebf[(size_t)NTOT * DIM];   // 16 MB
__device__ unsigned g_min_key;
__device__ unsigned g_max_key;

__device__ __forceinline__ unsigned f2key(float f) {
    unsigned b = __float_as_uint(f);
    return (b & 0x80000000u) ? ~b : (b | 0x80000000u);
}
__device__ __forceinline__ float key2f(unsigned k) {
    unsigned b = (k & 0x80000000u) ? (k ^ 0x80000000u) : ~k;
    return __uint_as_float(b);
}

// ---------------------------------------------------------------------------
// PTX helpers (sm_90-baseline)
// ---------------------------------------------------------------------------
__device__ __forceinline__ uint32_t smem_u32(const void* p) {
    uint32_t a;
    asm("{ .reg .u64 t; cvta.to.shared.u64 t, %1; cvt.u32.u64 %0, t; }" : "=r"(a) : "l"(p));
    return a;
}

#define CP_ASYNC16(s, g) \
    asm volatile("cp.async.cg.shared.global [%0], [%1], 16;" :: "r"(s), "l"(g) : "memory")

#define MBAR_INIT(a, c) \
    asm volatile("mbarrier.init.shared.b64 [%0], %1;" :: "r"(a), "r"(c) : "memory")
#define MBAR_ARRIVE(a) \
    asm volatile("mbarrier.arrive.shared.b64 _, [%0];" :: "r"(a) : "memory")
// .noinc: async arrival counts against the init expected count.
#define CP_MBAR_ARRIVE_NOINC(a) \
    asm volatile("cp.async.mbarrier.arrive.noinc.shared.b64 [%0];" :: "r"(a) : "memory")

__device__ __forceinline__ void mbar_wait(uint32_t mbar, uint32_t parity) {
    uint32_t done;
    asm volatile(
        "{ .reg .pred p; mbarrier.try_wait.parity.acquire.cta.shared::cta.b64 p, [%1], %2; selp.b32 %0, 1, 0, p; }"
        : "=r"(done) : "r"(mbar), "r"(parity) : "memory");
    if (!done) {
        asm volatile(
            "{ .reg .pred P1;\n"
            "WL_%=: mbarrier.try_wait.parity.acquire.cta.shared::cta.b64 P1, [%0], %1, 0x989680;\n"
            "@P1 bra.uni WD_%=;\n"
            "bra.uni WL_%=;\n"
            "WD_%=: }"
            :: "r"(mbar), "r"(parity) : "memory");
    }
}

#define LDMATRIX_X4(r0, r1, r2, r3, addr) \
    asm volatile("ldmatrix.sync.aligned.m8n8.x4.shared.b16 {%0,%1,%2,%3}, [%4];" \
        : "=r"(r0), "=r"(r1), "=r"(r2), "=r"(r3) : "r"(addr))

#define MMA_16816(c0, c1, c2, c3, a0, a1, a2, a3, b0, b1) \
    asm volatile("mma.sync.aligned.m16n8k16.row.col.f32.bf16.bf16.f32 " \
        "{%0,%1,%2,%3}, {%4,%5,%6,%7}, {%8,%9}, {%0,%1,%2,%3};" \
        : "+f"(c0), "+f"(c1), "+f"(c2), "+f"(c3) \
        : "r"(a0), "r"(a1), "r"(a2), "r"(a3), "r"(b0), "r"(b1))

__device__ __forceinline__ uint32_t swz(uint32_t off) {
    return off ^ ((off >> 3) & 0x70);
}

// work item w (0..8255) -> ti. S(ti) = ti*(257-ti)/2 items precede row ti.
__device__ __forceinline__ int ti_of(int w) {
    int ti = (int)((257.0f - sqrtf((float)(66049 - 8 * w))) * 0.5f);
    if (ti > 0 && ti * (257 - ti) / 2 > w) ti--;
    if ((ti + 1) * (256 - ti) / 2 <= w) ti++;
    return ti;
}

// ---------------------------------------------------------------------------
// fp32 -> bf16 convert: 8 elems/thread, 2 independent float4 loads, 20 regs
// (measured optimum: ~9.2us) + fused min/max key init
// ---------------------------------------------------------------------------
__device__ __forceinline__ uint32_t pack_bf2(float a, float b) {
    uint32_t lo = (uint32_t)__bfloat16_as_ushort(__float2bfloat16_rn(a));
    uint32_t hi = (uint32_t)__bfloat16_as_ushort(__float2bfloat16_rn(b));
    return lo | (hi << 16);
}

__global__ __launch_bounds__(256) void lp_convert_kernel(const float* __restrict__ E) {
    if (blockIdx.x == 0 && threadIdx.x == 0) {
        g_min_key = 0xFFFFFFFFu;
        g_max_key = 0u;
    }
    size_t t = (size_t)blockIdx.x * blockDim.x + threadIdx.x;   // 0..1048575
    const float4* src = (const float4*)(E + t * 8);
    float4 f0 = src[0], f1 = src[1];
    uint4 p = make_uint4(pack_bf2(f0.x, f0.y), pack_bf2(f0.z, f0.w),
                         pack_bf2(f1.x, f1.y), pack_bf2(f1.z, f1.w));
    *(uint4*)(g_Ebf + t * 8) = p;
}

// ---------------------------------------------------------------------------
// GEMM: 8256 CTAs (tj >= ti), 2 CTAs/SM, mbarrier producer/consumer ring.
// Main loop byte-identical to Round 14 (best measured). R15 change: epilogue
// min/max reduced block-wide in smem -> 2 atomics per CTA instead of 16.
// ---------------------------------------------------------------------------
__global__ __launch_bounds__(THREADS, 2) void lp_mm_kernel(float* __restrict__ out) {
    const int w  = blockIdx.x;
    const int ti = ti_of(w);
    const int tj = ti + (w - ti * (257 - ti) / 2);

    extern __shared__ __align__(128) unsigned char smem[];
    const uint32_t sb = smem_u32(smem);
    const uint32_t mb_full  = sb + SOFF_MBAR;        // 3 x 8B
    const uint32_t mb_empty = sb + SOFF_MBAR + 24;   // 3 x 8B

    __shared__ float red_min[8], red_max[8];         // tiny static scratch

    const int tid  = threadIdx.x;
    const int wid  = tid >> 5;
    const int lane = tid & 31;
    const int wm   = (wid >> 1) * 32;    // 0,32,64,96
    const int wn   = (wid & 1) * 64;     // 0 or 64

    if (tid == 0) {
        #pragma unroll
        for (int s = 0; s < NSTG; s++) {
            MBAR_INIT(mb_full  + s * 8, THREADS);
            MBAR_INIT(mb_empty + s * 8, 8);
        }
    }
    __syncthreads();   // publish mbarrier init

    const __nv_bfloat16* __restrict__ Abase = g_Ebf + (size_t)ti * BM * DIM;
    const __nv_bfloat16* __restrict__ Bbase = g_Ebf + (size_t)tj * BN * DIM;

    auto load_chunk = [&](int kt) {
        const int st = kt % NSTG;
        const uint32_t sA  = sb + st * SA_BYTES;
        const uint32_t sBb = sb + SOFF_B + st * SB_BYTES;
        const __nv_bfloat16* Asrc = Abase + kt * BK;
        const __nv_bfloat16* Bsrc = Bbase + kt * BK;
        #pragma unroll
        for (int i = 0; i < 4; i++) {
            int id  = tid + i * THREADS;
            int row = id >> 3, k8 = id & 7;
            CP_ASYNC16(sA + swz((uint32_t)(row * 128 + k8 * 16)),
                       Asrc + (size_t)row * DIM + k8 * 8);
        }
        #pragma unroll
        for (int i = 0; i < 4; i++) {
            int id  = tid + i * THREADS;
            int row = id >> 3, k8 = id & 7;
            CP_ASYNC16(sBb + swz((uint32_t)(row * 128 + k8 * 16)),
                       Bsrc + (size_t)row * DIM + k8 * 8);
        }
        CP_MBAR_ARRIVE_NOINC(mb_full + st * 8);
    };

    // prologue: fill all 3 stages (fresh, no empty-wait needed)
    load_chunk(0); load_chunk(1); load_chunk(2);

    const int arow_lo = (lane & 15);
    const int akb     = ((lane >> 4) << 4);
    const int brow_in = ((lane >> 4) << 3) + (lane & 7);
    const int bkb     = ((lane >> 3) & 1) << 4;

    float acc[2][8][4];
    #pragma unroll
    for (int mt = 0; mt < 2; mt++)
        #pragma unroll
        for (int n8 = 0; n8 < 8; n8++)
            #pragma unroll
            for (int r = 0; r < 4; r++)
                acc[mt][n8][r] = 0.0f;

    // wait for chunk 0 before the loop; in-loop waits are hoisted
    mbar_wait(mb_full + 0, 0);

    #pragma unroll 1
    for (int kt = 0; kt < KT; kt++) {
        const int st = kt % NSTG;
        const uint32_t sA = sb + st * SA_BYTES;
        const uint32_t sB = sb + SOFF_B + st * SB_BYTES;

        #pragma unroll
        for (int kk = 0; kk < 4; kk++) {
            uint32_t a[2][4];
            #pragma unroll
            for (int mt = 0; mt < 2; mt++) {
                int row = wm + mt * 16 + arow_lo;
                uint32_t kb = (uint32_t)(kk * 32 + akb);
                uint32_t addr = sA + row * 128 + (kb ^ ((row & 7) << 4));
                LDMATRIX_X4(a[mt][0], a[mt][1], a[mt][2], a[mt][3], addr);
            }
            uint32_t b[4][4];
            #pragma unroll
            for (int nb = 0; nb < 4; nb++) {
                int row = wn + nb * 16 + brow_in;
                uint32_t kb = (uint32_t)(kk * 32 + bkb);
                uint32_t addr = sB + row * 128 + (kb ^ ((row & 7) << 4));
                LDMATRIX_X4(b[nb][0], b[nb][1], b[nb][2], b[nb][3], addr);
            }
            if (kk == 3) {
                // this warp's last read of stage st: release it
                if (lane == 0) MBAR_ARRIVE(mb_empty + st * 8);
                // resolve next stage's full-wait behind the queued MMAs
                if (kt + 1 < KT)
                    mbar_wait(mb_full + ((kt + 1) % NSTG) * 8,
                              (uint32_t)(((kt + 1) / 3) & 1));
            }
            #pragma unroll
            for (int mt = 0; mt < 2; mt++)
                #pragma unroll
                for (int nb = 0; nb < 4; nb++) {
                    MMA_16816(acc[mt][2*nb][0], acc[mt][2*nb][1],
                              acc[mt][2*nb][2], acc[mt][2*nb][3],
                              a[mt][0], a[mt][1], a[mt][2], a[mt][3],
                              b[nb][0], b[nb][1]);
                    MMA_16816(acc[mt][2*nb+1][0], acc[mt][2*nb+1][1],
                              acc[mt][2*nb+1][2], acc[mt][2*nb+1][3],
                              a[mt][0], a[mt][1], a[mt][2], a[mt][3],
                              b[nb][2], b[nb][3]);
                }
        }

        // refill: chunk c = kt+3 reuses stage st; wait until all 8 warps
        // released it, then issue the copies.
        const int c = kt + 3;
        if (c < KT) {
            mbar_wait(mb_empty + st * 8, (uint32_t)(((c / 3) - 1) & 1));
            load_chunk(c);
        }
    }

    // ------------------- epilogue -------------------
    float lmin = 3.4e38f, lmax = -3.4e38f;
    #pragma unroll
    for (int mt = 0; mt < 2; mt++)
        #pragma unroll
        for (int n8 = 0; n8 < 8; n8++)
            #pragma unroll
            for (int r = 0; r < 4; r++) {
                float v = acc[mt][n8][r];
                lmin = fminf(lmin, v);
                lmax = fmaxf(lmax, v);
            }

    // diagonal tile == graph ti: raw values straight into out's triu layout
    if (ti == tj) {
        float* o = out + (size_t)ti * NPAIR;
        #pragma unroll
        for (int mt = 0; mt < 2; mt++) {
            #pragma unroll
            for (int n8 = 0; n8 < 8; n8++) {
                #pragma unroll
                for (int r = 0; r < 4; r++) {
                    int mg = wm + mt * 16 + (lane >> 2) + ((r >> 1) << 3);
                    int ng = wn + n8 * 8 + ((lane & 3) << 1) + (r & 1);
                    if (ng > mg) {
                        int p = mg * (GSZ - 1) - (mg * (mg - 1)) / 2 + (ng - mg - 1);
                        o[p] = acc[mt][n8][r];
                    }
                }
            }
        }
    }

    // warp shfl reduce -> smem -> warp 0 -> 2 atomics per CTA
    #pragma unroll
    for (int off = 16; off > 0; off >>= 1) {
        lmin = fminf(lmin, __shfl_xor_sync(0xffffffffu, lmin, off));
        lmax = fmaxf(lmax, __shfl_xor_sync(0xffffffffu, lmax, off));
    }
    if (lane == 0) { red_min[wid] = lmin; red_max[wid] = lmax; }
    __syncthreads();   // after main loop; does not perturb the pipeline
    if (tid == 0) {
        float m = red_min[0], M = red_max[0];
        #pragma unroll
        for (int q = 1; q < 8; q++) {
            m = fminf(m, red_min[q]);
            M = fmaxf(M, red_max[q]);
        }
        atomicMin(&g_min_key, f2key(m));
        atomicMax(&g_max_key, f2key(M));
    }
}

// ---------------------------------------------------------------------------
// flat in-place normalize: out[i] = (out[i] - m) * inv, float4 vectorized
// ---------------------------------------------------------------------------
__global__ __launch_bounds__(256) void lp_norm_kernel(float* __restrict__ out) {
    const float m = key2f(g_min_key);
    const float M = key2f(g_max_key);
    const float inv = 1.0f / (M - m + 1e-7f);
    const int i = blockIdx.x * 256 + threadIdx.x;
    float4* o4 = (float4*)out;
    float4 v = o4[i];
    v.x = (v.x - m) * inv;
    v.y = (v.y - m) * inv;
    v.z = (v.z - m) * inv;
    v.w = (v.w - m) * inv;
    o4[i] = v;
}

// ---------------------------------------------------------------------------
// kernel_launch
// ---------------------------------------------------------------------------
extern "C" void kernel_launch(void* const* d_in, const int* in_sizes, int n_in,
                              void* d_out, int out_size)
{
    const float* E = (const float*)d_in[0];
    float* out = (float*)d_out;
    (void)in_sizes; (void)n_in; (void)out_size;

    static bool attr_set = false;
    if (!attr_set) {
        cudaFuncSetAttribute(lp_mm_kernel,
                             cudaFuncAttributeMaxDynamicSharedMemorySize, SMEM_TOTAL);
        attr_set = true;
    }

    lp_convert_kernel<<<4096, 256>>>(E);
    lp_mm_kernel<<<NITEMS, THREADS, SMEM_TOTAL>>>(out);
    lp_norm_kernel<<<NOUT / 1024, 256>>>(out);
}

// round 16
// speedup vs baseline: 1.0099x; 1.0099x over previous
#include <cuda_runtime.h>
#include <cuda_bf16.h>
#include <cstdint>
#include <cstddef>

// ---------------------------------------------------------------------------
// Problem constants
// ---------------------------------------------------------------------------
#define NG    128
#define GSZ   128
#define DIM   512
#define NTOT  (NG * GSZ)               // 16384
#define NPAIR (GSZ * (GSZ - 1) / 2)    // 8128
#define NOUT  (NG * NPAIR)             // 1,040,384

// GEMM tiling: 128x128 CTA tile, 256 threads, 2 CTAs/SM
#define BM 128
#define BN 128
#define BK 64
#define KT (DIM / BK)                  // 8 k-chunks per tile
#define NSTG 3
#define THREADS 256
#define NITEMS 8256                    // # of 128x128 tiles with tj >= ti

#define SA_BYTES (BM * BK * 2)         // 16 KB
#define SB_BYTES (BN * BK * 2)         // 16 KB
#define SOFF_B   (NSTG * SA_BYTES)
#define SOFF_MBAR (NSTG * (SA_BYTES + SB_BYTES))     // 98304
#define SMEM_TOTAL (SOFF_MBAR + 64)                  // + mbarriers

// ---------------------------------------------------------------------------
// Device globals
// ---------------------------------------------------------------------------
__device__ __align__(16) __nv_bfloat16 g_Ebf[(size_t)NTOT * DIM];   // 16 MB
__device__ unsigned g_min_key;
__device__ unsigned g_max_key;

__device__ __forceinline__ unsigned f2key(float f) {
    unsigned b = __float_as_uint(f);
    return (b & 0x80000000u) ? ~b : (b | 0x80000000u);
}
__device__ __forceinline__ float key2f(unsigned k) {
    unsigned b = (k & 0x80000000u) ? (k ^ 0x80000000u) : ~k;
    return __uint_as_float(b);
}

// ---------------------------------------------------------------------------
// PTX helpers (sm_90-baseline)
// ---------------------------------------------------------------------------
__device__ __forceinline__ uint32_t smem_u32(const void* p) {
    uint32_t a;
    asm("{ .reg .u64 t; cvta.to.shared.u64 t, %1; cvt.u32.u64 %0, t; }" : "=r"(a) : "l"(p));
    return a;
}

#define CP_ASYNC16(s, g) \
    asm volatile("cp.async.cg.shared.global [%0], [%1], 16;" :: "r"(s), "l"(g) : "memory")

#define MBAR_INIT(a, c) \
    asm volatile("mbarrier.init.shared.b64 [%0], %1;" :: "r"(a), "r"(c) : "memory")
#define MBAR_ARRIVE(a) \
    asm volatile("mbarrier.arrive.shared.b64 _, [%0];" :: "r"(a) : "memory")
// .noinc: async arrival counts against the init expected count.
#define CP_MBAR_ARRIVE_NOINC(a) \
    asm volatile("cp.async.mbarrier.arrive.noinc.shared.b64 [%0];" :: "r"(a) : "memory")

__device__ __forceinline__ void mbar_wait(uint32_t mbar, uint32_t parity) {
    uint32_t done;
    asm volatile(
        "{ .reg .pred p; mbarrier.try_wait.parity.acquire.cta.shared::cta.b64 p, [%1], %2; selp.b32 %0, 1, 0, p; }"
        : "=r"(done) : "r"(mbar), "r"(parity) : "memory");
    if (!done) {
        asm volatile(
            "{ .reg .pred P1;\n"
            "WL_%=: mbarrier.try_wait.parity.acquire.cta.shared::cta.b64 P1, [%0], %1, 0x989680;\n"
            "@P1 bra.uni WD_%=;\n"
            "bra.uni WL_%=;\n"
            "WD_%=: }"
            :: "r"(mbar), "r"(parity) : "memory");
    }
}

#define LDMATRIX_X4(r0, r1, r2, r3, addr) \
    asm volatile("ldmatrix.sync.aligned.m8n8.x4.shared.b16 {%0,%1,%2,%3}, [%4];" \
        : "=r"(r0), "=r"(r1), "=r"(r2), "=r"(r3) : "r"(addr))

#define MMA_16816(c0, c1, c2, c3, a0, a1, a2, a3, b0, b1) \
    asm volatile("mma.sync.aligned.m16n8k16.row.col.f32.bf16.bf16.f32 " \
        "{%0,%1,%2,%3}, {%4,%5,%6,%7}, {%8,%9}, {%0,%1,%2,%3};" \
        : "+f"(c0), "+f"(c1), "+f"(c2), "+f"(c3) \
        : "r"(a0), "r"(a1), "r"(a2), "r"(a3), "r"(b0), "r"(b1))

__device__ __forceinline__ uint32_t swz(uint32_t off) {
    return off ^ ((off >> 3) & 0x70);
}

// work item w (0..8255) -> ti. S(ti) = ti*(257-ti)/2 items precede row ti.
__device__ __forceinline__ int ti_of(int w) {
    int ti = (int)((257.0f - sqrtf((float)(66049 - 8 * w))) * 0.5f);
    if (ti > 0 && ti * (257 - ti) / 2 > w) ti--;
    if ((ti + 1) * (256 - ti) / 2 <= w) ti++;
    return ti;
}

// ---------------------------------------------------------------------------
// fp32 -> bf16 convert: 8 elems/thread, 2 independent float4 loads, 20 regs
// (measured optimum: ~9.2us) + fused min/max key init
// ---------------------------------------------------------------------------
__device__ __forceinline__ uint32_t pack_bf2(float a, float b) {
    uint32_t lo = (uint32_t)__bfloat16_as_ushort(__float2bfloat16_rn(a));
    uint32_t hi = (uint32_t)__bfloat16_as_ushort(__float2bfloat16_rn(b));
    return lo | (hi << 16);
}

__global__ __launch_bounds__(256) void lp_convert_kernel(const float* __restrict__ E) {
    if (blockIdx.x == 0 && threadIdx.x == 0) {
        g_min_key = 0xFFFFFFFFu;
        g_max_key = 0u;
    }
    size_t t = (size_t)blockIdx.x * blockDim.x + threadIdx.x;   // 0..1048575
    const float4* src = (const float4*)(E + t * 8);
    float4 f0 = src[0], f1 = src[1];
    uint4 p = make_uint4(pack_bf2(f0.x, f0.y), pack_bf2(f0.z, f0.w),
                         pack_bf2(f1.x, f1.y), pack_bf2(f1.z, f1.w));
    *(uint4*)(g_Ebf + t * 8) = p;
}

// ---------------------------------------------------------------------------
// GEMM: 8256 CTAs (tj >= ti), 2 CTAs/SM, mbarrier producer/consumer ring.
// Byte-identical to Round 14 — the best measured configuration (295.3us):
// warp-sliding pipeline, hoisted full-waits, per-warp epilogue atomics with
// NO trailing block barrier (R15 showed the barrier costs ~2.7us).
// ---------------------------------------------------------------------------
__global__ __launch_bounds__(THREADS, 2) void lp_mm_kernel(float* __restrict__ out) {
    const int w  = blockIdx.x;
    const int ti = ti_of(w);
    const int tj = ti + (w - ti * (257 - ti) / 2);

    extern __shared__ __align__(128) unsigned char smem[];
    const uint32_t sb = smem_u32(smem);
    const uint32_t mb_full  = sb + SOFF_MBAR;        // 3 x 8B
    const uint32_t mb_empty = sb + SOFF_MBAR + 24;   // 3 x 8B

    const int tid  = threadIdx.x;
    const int wid  = tid >> 5;
    const int lane = tid & 31;
    const int wm   = (wid >> 1) * 32;    // 0,32,64,96
    const int wn   = (wid & 1) * 64;     // 0 or 64

    if (tid == 0) {
        #pragma unroll
        for (int s = 0; s < NSTG; s++) {
            MBAR_INIT(mb_full  + s * 8, THREADS);
            MBAR_INIT(mb_empty + s * 8, 8);
        }
    }
    __syncthreads();   // only block barrier: publish mbarrier init

    const __nv_bfloat16* __restrict__ Abase = g_Ebf + (size_t)ti * BM * DIM;
    const __nv_bfloat16* __restrict__ Bbase = g_Ebf + (size_t)tj * BN * DIM;

    auto load_chunk = [&](int kt) {
        const int st = kt % NSTG;
        const uint32_t sA  = sb + st * SA_BYTES;
        const uint32_t sBb = sb + SOFF_B + st * SB_BYTES;
        const __nv_bfloat16* Asrc = Abase + kt * BK;
        const __nv_bfloat16* Bsrc = Bbase + kt * BK;
        #pragma unroll
        for (int i = 0; i < 4; i++) {
            int id  = tid + i * THREADS;
            int row = id >> 3, k8 = id & 7;
            CP_ASYNC16(sA + swz((uint32_t)(row * 128 + k8 * 16)),
                       Asrc + (size_t)row * DIM + k8 * 8);
        }
        #pragma unroll
        for (int i = 0; i < 4; i++) {
            int id  = tid + i * THREADS;
            int row = id >> 3, k8 = id & 7;
            CP_ASYNC16(sBb + swz((uint32_t)(row * 128 + k8 * 16)),
                       Bsrc + (size_t)row * DIM + k8 * 8);
        }
        CP_MBAR_ARRIVE_NOINC(mb_full + st * 8);
    };

    // prologue: fill all 3 stages (fresh, no empty-wait needed)
    load_chunk(0); load_chunk(1); load_chunk(2);

    const int arow_lo = (lane & 15);
    const int akb     = ((lane >> 4) << 4);
    const int brow_in = ((lane >> 4) << 3) + (lane & 7);
    const int bkb     = ((lane >> 3) & 1) << 4;

    float acc[2][8][4];
    #pragma unroll
    for (int mt = 0; mt < 2; mt++)
        #pragma unroll
        for (int n8 = 0; n8 < 8; n8++)
            #pragma unroll
            for (int r = 0; r < 4; r++)
                acc[mt][n8][r] = 0.0f;

    // wait for chunk 0 before the loop; in-loop waits are hoisted
    mbar_wait(mb_full + 0, 0);

    #pragma unroll 1
    for (int kt = 0; kt < KT; kt++) {
        const int st = kt % NSTG;
        const uint32_t sA = sb + st * SA_BYTES;
        const uint32_t sB = sb + SOFF_B + st * SB_BYTES;

        #pragma unroll
        for (int kk = 0; kk < 4; kk++) {
            uint32_t a[2][4];
            #pragma unroll
            for (int mt = 0; mt < 2; mt++) {
                int row = wm + mt * 16 + arow_lo;
                uint32_t kb = (uint32_t)(kk * 32 + akb);
                uint32_t addr = sA + row * 128 + (kb ^ ((row & 7) << 4));
                LDMATRIX_X4(a[mt][0], a[mt][1], a[mt][2], a[mt][3], addr);
            }
            uint32_t b[4][4];
            #pragma unroll
            for (int nb = 0; nb < 4; nb++) {
                int row = wn + nb * 16 + brow_in;
                uint32_t kb = (uint32_t)(kk * 32 + bkb);
                uint32_t addr = sB + row * 128 + (kb ^ ((row & 7) << 4));
                LDMATRIX_X4(b[nb][0], b[nb][1], b[nb][2], b[nb][3], addr);
            }
            if (kk == 3) {
                // this warp's last read of stage st: release it
                if (lane == 0) MBAR_ARRIVE(mb_empty + st * 8);
                // resolve next stage's full-wait behind the queued MMAs
                if (kt + 1 < KT)
                    mbar_wait(mb_full + ((kt + 1) % NSTG) * 8,
                              (uint32_t)(((kt + 1) / 3) & 1));
            }
            #pragma unroll
            for (int mt = 0; mt < 2; mt++)
                #pragma unroll
                for (int nb = 0; nb < 4; nb++) {
                    MMA_16816(acc[mt][2*nb][0], acc[mt][2*nb][1],
                              acc[mt][2*nb][2], acc[mt][2*nb][3],
                              a[mt][0], a[mt][1], a[mt][2], a[mt][3],
                              b[nb][0], b[nb][1]);
                    MMA_16816(acc[mt][2*nb+1][0], acc[mt][2*nb+1][1],
                              acc[mt][2*nb+1][2], acc[mt][2*nb+1][3],
                              a[mt][0], a[mt][1], a[mt][2], a[mt][3],
                              b[nb][2], b[nb][3]);
                }
        }

        // refill: chunk c = kt+3 reuses stage st; wait until all 8 warps
        // released it, then issue the copies.
        const int c = kt + 3;
        if (c < KT) {
            mbar_wait(mb_empty + st * 8, (uint32_t)(((c / 3) - 1) & 1));
            load_chunk(c);
        }
    }

    // ------------------- epilogue -------------------
    float lmin = 3.4e38f, lmax = -3.4e38f;
    #pragma unroll
    for (int mt = 0; mt < 2; mt++)
        #pragma unroll
        for (int n8 = 0; n8 < 8; n8++)
            #pragma unroll
            for (int r = 0; r < 4; r++) {
                float v = acc[mt][n8][r];
                lmin = fminf(lmin, v);
                lmax = fmaxf(lmax, v);
            }

    // diagonal tile == graph ti: raw values straight into out's triu layout
    if (ti == tj) {
        float* o = out + (size_t)ti * NPAIR;
        #pragma unroll
        for (int mt = 0; mt < 2; mt++) {
            #pragma unroll
            for (int n8 = 0; n8 < 8; n8++) {
                #pragma unroll
                for (int r = 0; r < 4; r++) {
                    int mg = wm + mt * 16 + (lane >> 2) + ((r >> 1) << 3);
                    int ng = wn + n8 * 8 + ((lane & 3) << 1) + (r & 1);
                    if (ng > mg) {
                        int p = mg * (GSZ - 1) - (mg * (mg - 1)) / 2 + (ng - mg - 1);
                        o[p] = acc[mt][n8][r];
                    }
                }
            }
        }
    }

    // warp reduce + one atomic pair per warp (no trailing block barrier)
    #pragma unroll
    for (int off = 16; off > 0; off >>= 1) {
        lmin = fminf(lmin, __shfl_xor_sync(0xffffffffu, lmin, off));
        lmax = fmaxf(lmax, __shfl_xor_sync(0xffffffffu, lmax, off));
    }
    if (lane == 0) {
        atomicMin(&g_min_key, f2key(lmin));
        atomicMax(&g_max_key, f2key(lmax));
    }
}

// ---------------------------------------------------------------------------
// flat in-place normalize: out[i] = (out[i] - m) * inv, float4 vectorized
// ---------------------------------------------------------------------------
__global__ __launch_bounds__(256) void lp_norm_kernel(float* __restrict__ out) {
    const float m = key2f(g_min_key);
    const float M = key2f(g_max_key);
    const float inv = 1.0f / (M - m + 1e-7f);
    const int i = blockIdx.x * 256 + threadIdx.x;
    float4* o4 = (float4*)out;
    float4 v = o4[i];
    v.x = (v.x - m) * inv;
    v.y = (v.y - m) * inv;
    v.z = (v.z - m) * inv;
    v.w = (v.w - m) * inv;
    o4[i] = v;
}

// ---------------------------------------------------------------------------
// kernel_launch
// ---------------------------------------------------------------------------
extern "C" void kernel_launch(void* const* d_in, const int* in_sizes, int n_in,
                              void* d_out, int out_size)
{
    const float* E = (const float*)d_in[0];
    float* out = (float*)d_out;
    (void)in_sizes; (void)n_in; (void)out_size;

    static bool attr_set = false;
    if (!attr_set) {
        cudaFuncSetAttribute(lp_mm_kernel,
                             cudaFuncAttributeMaxDynamicSharedMemorySize, SMEM_TOTAL);
        attr_set = true;
    }

    lp_convert_kernel<<<4096, 256>>>(E);
    lp_mm_kernel<<<NITEMS, THREADS, SMEM_TOTAL>>>(out);
    lp_norm_kernel<<<NOUT / 1024, 256>>>(out);
}